// round 7
// baseline (speedup 1.0000x reference)
#include <cuda_runtime.h>
#include <cuda_fp16.h>

namespace {

constexpr int Bsz = 32768;
constexpr int NIN = 41;
constexpr int WPB = 4;
constexpr unsigned FULL = 0xffffffffu;

__device__ __forceinline__ float clamp1(float w) {
    return fminf(fmaxf(w, -1.f), 1.f);
}
__device__ __forceinline__ float clipv(float w) {
    return fminf(fmaxf(w, -0.2f), 1.0f);
}
__device__ __forceinline__ float blurcoef(int x, int y) {
    int d = x - y; if (d < 0) d = -d;
    return (d == 0) ? 0.8f : (d == 1 ? 0.1f : 0.f);
}

__global__ __launch_bounds__(WPB * 32, 7) void pgnet_kernel(
    const float* __restrict__ inp,
    const float* __restrict__ fpg_w,
    const float* __restrict__ fpg_b,
    const float* __restrict__ rpg_w,
    const float* __restrict__ rpg_b,
    const float* __restrict__ pgctrl_w,
    const float* __restrict__ pgctrl_b,
    float* __restrict__ out)
{
    __shared__ float s_wsum[8][44];
    __shared__ float s_wc2[8][44];
    __shared__ float s_pb[8];
    __shared__ float s_B3[8][9];
    __shared__ float s_B2[4][5];
    __shared__ float s_inp[WPB][44];
    __shared__ float s_rb[WPB][44];

    const int tid  = threadIdx.x;
    const int warp = tid >> 5;
    const int lane = tid & 31;
    const int b = blockIdx.x * WPB + warp;
    const int q   = lane >> 3;     // 0..3 : output-group / o mod 4 role
    const int j   = lane & 7;      // 0..7 : r role
    const int j2  = j >> 2;        // r-quad selector t
    const int j01 = j & 3;         // k-class (fpg) / i index (rpg)

    const float4* rw4 = (const float4*)(rpg_w + (long)b * 1312);
    const float4* fw4 = (const float4*)(fpg_w + (long)b * 1312);

    // ---- rpg_w: coalesced direct-to-register loads ----
    // float4 n = 32m + 8q + 2*j01 + j2  ->  (o = 4m+q, i = j01, r = 4*j2 + 0..3)
    __half2 wh[22];
    #pragma unroll
    for (int m = 0; m < 11; m++) {
        int o = 4 * m + q;
        float4 f;
        if (o < NIN) f = rw4[32 * m + 8 * q + 2 * j01 + j2];
        else         f = make_float4(0.f, 0.f, 0.f, 0.f);
        wh[2 * m]     = __floats2half2_rn(clamp1(f.x), clamp1(f.y));
        wh[2 * m + 1] = __floats2half2_rn(clamp1(f.z), clamp1(f.w));
    }

    // ---- per-warp vectors ----
    if (lane < NIN)      { s_inp[warp][lane]      = inp[b * NIN + lane];
                           s_rb[warp][lane]       = rpg_b[b * NIN + lane]; }
    if (lane + 32 < NIN) { s_inp[warp][lane + 32] = inp[b * NIN + lane + 32];
                           s_rb[warp][lane + 32]  = rpg_b[b * NIN + lane + 32]; }
    if (lane >= 9 && lane < 12) s_rb[warp][lane + 32] = 0.f;  // pad 41..43

    // ---- block-shared pgctrl tables + blur powers ----
    for (int idx = tid; idx < 8 * 44; idx += WPB * 32) {
        int rr = idx / 44, oo = idx % 44;
        float w2 = (oo < NIN) ? pgctrl_w[rr * 86 + 45 + oo] : 0.f;
        s_wc2[rr][oo]  = w2;
        s_wsum[rr][oo] = (oo < NIN) ? (pgctrl_w[rr * 86 + oo] + w2) : 0.f;
    }
    if (tid < 8) s_pb[tid] = pgctrl_b[tid];
    if (tid < 64) {
        int r0 = tid >> 3, c0 = tid & 7;
        float acc = 0.f;
        #pragma unroll
        for (int k = 0; k < 8; k++)
            #pragma unroll
            for (int m = 0; m < 8; m++)
                acc += blurcoef(r0, k) * blurcoef(k, m) * blurcoef(m, c0);
        s_B3[r0][c0] = acc;
    }
    if (tid >= 64 && tid < 80) {
        int t = tid - 64, r0 = t >> 2, c0 = t & 3;
        float acc = 0.f;
        #pragma unroll
        for (int k = 0; k < 4; k++)
            acc += blurcoef(r0, k) * blurcoef(k, c0);
        s_B2[r0][c0] = acc;
    }

    const float fb = fpg_b[b * 4 + q];
    __syncthreads();

    const float* si = s_inp[warp];

    // ---- fpg dot, direct from global: lane covers (o=q, r=4*j2+t', k ≡ j01 mod 4)
    // float4 n = q*82 + 2k + j2  ->  (o=q, k, r = 4*j2 + 0..3)
    float a0 = 0.f, a1 = 0.f, a2 = 0.f, a3 = 0.f;
    #pragma unroll
    for (int m = 0; m < 11; m++) {
        int k = j01 + 4 * m;
        if (k <= 40) {
            float4 g = fw4[q * 82 + 2 * k + j2];
            float x = si[k];
            a0 = fmaf(clamp1(g.x), x, a0);
            a1 = fmaf(clamp1(g.y), x, a1);
            a2 = fmaf(clamp1(g.z), x, a2);
            a3 = fmaf(clamp1(g.w), x, a3);
        }
    }
    // reduce over the 4 k-classes (lanes differing in j0,j1; j2/q preserved)
    a0 += __shfl_xor_sync(FULL, a0, 1);  a0 += __shfl_xor_sync(FULL, a0, 2);
    a1 += __shfl_xor_sync(FULL, a1, 1);  a1 += __shfl_xor_sync(FULL, a1, 2);
    a2 += __shfl_xor_sync(FULL, a2, 1);  a2 += __shfl_xor_sync(FULL, a2, 2);
    a3 += __shfl_xor_sync(FULL, a3, 1);  a3 += __shfl_xor_sync(FULL, a3, 2);
    // lane (q,j) wants fdot(o=q, r=j): r = 4*j2 + t'  ->  t' = j01
    float f01 = (j & 1) ? a1 : a0;
    float f23 = (j & 1) ? a3 : a2;
    const float fdot = (j & 2) ? f23 : f01;

    // ---- A_j: iteration-invariant rc preactivation ----
    float A = s_pb[j];
    #pragma unroll
    for (int i = 0; i < NIN; i++) A = fmaf(si[i], s_wsum[j][i], A);

    float l1i[11];
    #pragma unroll
    for (int s = 0; s < 11; s++) l1i[s] = 0.f;
    float rc = 0.f, l2v = 0.f;

    #pragma unroll
    for (int it = 0; it < 2; it++) {
        // ---- D_j = sum_o l1i[o] * Wc[j,45+o] (zero on iter 0) ----
        float D = 0.f;
        if (it > 0) {
            #pragma unroll
            for (int s = 0; s < 11; s++)
                D = fmaf(l1i[s], s_wc2[j][4 * s + q], D);
            D += __shfl_xor_sync(FULL, D, 8);
            D += __shfl_xor_sync(FULL, D, 16);
        }

        // pre-blur rc value
        float x = A - D;
        x = (x >= 0.f) ? x : 0.2f * x;
        float v = clipv(0.4f * x);

        // gather the 8 pre-blur values; own rc row via dense blur^3
        float vv[8];
        #pragma unroll
        for (int k = 0; k < 8; k++)
            vv[k] = __shfl_sync(FULL, v, (lane & 24) | k);
        {
            float acc = 0.f;
            #pragma unroll
            for (int m = 0; m < 8; m++) acc = fmaf(s_B3[j][m], vv[m], acc);
            rc = acc;
        }
        // the 4 rc values this lane's rpg slice needs: r = 4*j2 + t'
        float rcg[4];
        #pragma unroll
        for (int t = 0; t < 4; t++)
            rcg[t] = __shfl_sync(FULL, rc, (lane & 24) | (4 * j2 + t));

        // ---- fpg -> l2: scale + 8-lane reduce + dense blur^2 ----
        float acc = fdot * rc;
        acc += __shfl_xor_sync(FULL, acc, 1);
        acc += __shfl_xor_sync(FULL, acc, 2);
        acc += __shfl_xor_sync(FULL, acc, 4);
        float t2 = clipv(0.1f * (acc + fb));
        float t2a = __shfl_xor_sync(FULL, t2, 8);
        float t2b = __shfl_xor_sync(FULL, t2, 16);
        float t2c = __shfl_xor_sync(FULL, t2, 24);
        float tq[4];
        tq[q] = t2; tq[q ^ 1] = t2a; tq[q ^ 2] = t2b; tq[q ^ 3] = t2c;
        float l2all[4];
        #pragma unroll
        for (int i = 0; i < 4; i++) {
            float a2v = 0.f;
            #pragma unroll
            for (int m = 0; m < 4; m++) a2v = fmaf(s_B2[i][m], tq[m], a2v);
            l2all[i] = a2v;
        }
        l2v = l2all[q];

        // pp[t'] = l2[i=j01] * rc[4*j2+t']
        float l01 = (j & 1) ? l2all[1] : l2all[0];
        float l23 = (j & 1) ? l2all[3] : l2all[2];
        float l2i = (j & 2) ? l23 : l01;
        float pp0 = l2i * rcg[0];
        float pp1 = l2i * rcg[1];
        float pp2 = l2i * rcg[2];
        float pp3 = l2i * rcg[3];

        // ---- rpg -> l1i: lane slice (o=4s+q, i=j01, r=4*j2+t'), reduce over j ----
        #pragma unroll
        for (int s = 0; s < 11; s++) {
            float2 w01 = __half22float2(wh[2 * s]);
            float2 w23 = __half22float2(wh[2 * s + 1]);
            float a = w01.x * pp0;
            a = fmaf(w01.y, pp1, a);
            a = fmaf(w23.x, pp2, a);
            a = fmaf(w23.y, pp3, a);
            a += __shfl_xor_sync(FULL, a, 1);
            a += __shfl_xor_sync(FULL, a, 2);
            a += __shfl_xor_sync(FULL, a, 4);
            l1i[s] = clipv(a + s_rb[warp][4 * s + q]);
        }
    }

    // ---- outputs: concat(l1i [B,41], l2 [B,4], rc [B,8]) ----
    if (j == 0) {
        #pragma unroll
        for (int s = 0; s < 11; s++) {
            int o = 4 * s + q;
            if (o < NIN) out[(long)b * NIN + o] = l1i[s];
        }
        out[(long)Bsz * NIN + b * 4 + q] = l2v;
    }
    if (lane < 8)
        out[(long)Bsz * 45 + b * 8 + lane] = rc;
}

} // namespace

extern "C" void kernel_launch(void* const* d_in, const int* in_sizes, int n_in,
                              void* d_out, int out_size) {
    pgnet_kernel<<<Bsz / WPB, WPB * 32>>>(
        (const float*)d_in[0],   // inp
        (const float*)d_in[1],   // fpg_w
        (const float*)d_in[2],   // fpg_b
        (const float*)d_in[3],   // rpg_w
        (const float*)d_in[4],   // rpg_b
        (const float*)d_in[5],   // pgctrl_w
        (const float*)d_in[6],   // pgctrl_b
        (float*)d_out);
}